// round 1
// baseline (speedup 1.0000x reference)
#include <cuda_runtime.h>

// Problem constants
// state: [4096, 4096] float32 (re and im separately), theta: scalar
// out[j]   needs state[j] and state[j^64]  (bit 6 flip = X on qubit 5 of 12)
// out_re = c*sr[j] + s*si[j^64]
// out_im = c*si[j] - s*sr[j^64]
// d_out layout: [out_re (4096*4096 floats) | out_im (4096*4096 floats)]

#define NELEM   (4096 * 4096)          // 16,777,216 elements per array
#define NPAIRT  (NELEM / 8)            // threads: each handles 2 float4 (8 elems)

__global__ void __launch_bounds__(256)
rx_gate_kernel(const float4* __restrict__ sr4,
               const float4* __restrict__ si4,
               const float*  __restrict__ theta,
               float4* __restrict__ ore4,
               float4* __restrict__ oim4)
{
    int t = blockIdx.x * blockDim.x + threadIdx.x;
    if (t >= NPAIRT) return;

    float half = 0.5f * theta[0];
    float s, c;
    sincosf(half, &s, &c);

    // Element group = 128 elements = 32 float4s. Low half: bit6=0 (first 16
    // float4s of the group), high half: bit6=1 (next 16 float4s).
    int grp = t >> 4;          // which 128-element group
    int w   = t & 15;          // which float4 within the low half
    int ilo = grp * 32 + w;    // float4 index, bit6 of element index = 0
    int ihi = ilo + 16;        // partner float4 (element index ^ 64)

    float4 a_re = sr4[ilo];
    float4 b_re = sr4[ihi];
    float4 a_im = si4[ilo];
    float4 b_im = si4[ihi];

    float4 o_re_lo, o_re_hi, o_im_lo, o_im_hi;

    o_re_lo.x = c * a_re.x + s * b_im.x;
    o_re_lo.y = c * a_re.y + s * b_im.y;
    o_re_lo.z = c * a_re.z + s * b_im.z;
    o_re_lo.w = c * a_re.w + s * b_im.w;

    o_re_hi.x = c * b_re.x + s * a_im.x;
    o_re_hi.y = c * b_re.y + s * a_im.y;
    o_re_hi.z = c * b_re.z + s * a_im.z;
    o_re_hi.w = c * b_re.w + s * a_im.w;

    o_im_lo.x = c * a_im.x - s * b_re.x;
    o_im_lo.y = c * a_im.y - s * b_re.y;
    o_im_lo.z = c * a_im.z - s * b_re.z;
    o_im_lo.w = c * a_im.w - s * b_re.w;

    o_im_hi.x = c * b_im.x - s * a_re.x;
    o_im_hi.y = c * b_im.y - s * a_re.y;
    o_im_hi.z = c * b_im.z - s * a_re.z;
    o_im_hi.w = c * b_im.w - s * a_re.w;

    ore4[ilo] = o_re_lo;
    ore4[ihi] = o_re_hi;
    oim4[ilo] = o_im_lo;
    oim4[ihi] = o_im_hi;
}

extern "C" void kernel_launch(void* const* d_in, const int* in_sizes, int n_in,
                              void* d_out, int out_size)
{
    const float4* sr4   = (const float4*)d_in[0];
    const float4* si4   = (const float4*)d_in[1];
    const float*  theta = (const float*)d_in[2];

    float* out   = (float*)d_out;
    float4* ore4 = (float4*)out;
    float4* oim4 = (float4*)(out + NELEM);

    const int threads = 256;
    const int blocks  = (NPAIRT + threads - 1) / threads;  // 8192
    rx_gate_kernel<<<blocks, threads>>>(sr4, si4, theta, ore4, oim4);
}